// round 7
// baseline (speedup 1.0000x reference)
#include <cuda_runtime.h>
#include <cuda_bf16.h>
#include <math.h>
#include <float.h>

// Problem constants
#define NB   64          // batch
#define NN   256         // nodes
#define TT   256         // feature dim
#define DD   64          // embedding dim
#define KK   16          // top-k

// Scratch (device globals: no allocation allowed)
__device__ float g_Y[NB * NN * TT];          // 16 MB intermediate Y = A @ x
__device__ int   g_adj[NN * KK];
__device__ float g_w[NN * KK];
__device__ int   g_cnt[NN];

// ---------------------------------------------------------------------------
// Kernel 1: build gated kNN graph.
// One block per destination node i; 256 threads (one per candidate j).
// Warp-shuffle argmax: 2 barriers/round instead of 8.
// ---------------------------------------------------------------------------
__global__ void build_graph_kernel(const float* __restrict__ emb,
                                   const float* __restrict__ logits,
                                   const float* __restrict__ gumbel)
{
    const int i    = blockIdx.x;
    const int t    = threadIdx.x;
    const int lane = t & 31;
    const int warp = t >> 5;

    __shared__ float wv[NN];      // working cos values
    __shared__ float wval[8];
    __shared__ int   widx[8];
    __shared__ int   sel[KK];
    __shared__ float sgate[KK];

    // cos(i, t)
    float dot = 0.f, ni = 0.f, nj = 0.f;
    #pragma unroll
    for (int d = 0; d < DD; d++) {
        float a = emb[i * DD + d];
        float b = emb[t * DD + d];
        dot += a * b;
        ni  += a * a;
        nj  += b * b;
    }
    wv[t] = dot / (sqrtf(ni) * sqrtf(nj));
    __syncthreads();

    // 16 rounds of block-argmax (tie -> lower index, matching jax top_k).
    // (max, min-index) lexicographic combine is associative -> any order OK.
    for (int r = 0; r < KK; r++) {
        float v  = wv[t];
        int   id = t;
        #pragma unroll
        for (int s = 16; s > 0; s >>= 1) {
            float v2 = __shfl_down_sync(0xffffffffu, v,  s);
            int   i2 = __shfl_down_sync(0xffffffffu, id, s);
            if (v2 > v || (v2 == v && i2 < id)) { v = v2; id = i2; }
        }
        if (lane == 0) { wval[warp] = v; widx[warp] = id; }
        __syncthreads();
        if (t == 0) {
            float bv = wval[0]; int bi = widx[0];
            #pragma unroll
            for (int w8 = 1; w8 < 8; w8++) {
                if (wval[w8] > bv || (wval[w8] == bv && widx[w8] < bi)) {
                    bv = wval[w8]; bi = widx[w8];
                }
            }
            sel[r] = bi;
            wv[bi] = -FLT_MAX;
        }
        __syncthreads();
    }

    // Gumbel-softmax hard gate per selected edge (threads 0..15 in parallel)
    if (t < KK) {
        int j = sel[t];
        long idx = (long)i * NN + j;
        float u0 = gumbel[idx * 2 + 0];
        float u1 = gumbel[idx * 2 + 1];
        float g0 = -logf(-logf(u0));
        float g1 = -logf(-logf(u1));
        float v0 = logits[idx * 2 + 0] + g0;
        float v1 = logits[idx * 2 + 1] + g1;
        float m  = fmaxf(v0, v1);
        float e0 = expf(v0 - m), e1 = expf(v1 - m);
        float s0 = e0 / (e0 + e1);
        float hard0 = (v0 >= v1) ? 1.0f : 0.0f;   // argmax ties -> index 0
        float gate = (hard0 + s0) - s0;           // straight-through forward value
        sgate[t] = gate;
    }
    __syncthreads();

    // Deterministic compaction by thread 0 (stable fp sum order downstream)
    if (t == 0) {
        int c = 0;
        for (int r = 0; r < KK; r++) {
            if (sgate[r] > 0.5f) {
                g_adj[i * KK + c] = sel[r];
                g_w[i * KK + c]   = 0.0625f * sgate[r];   // dinv_src*dinv_dst = 1/16 (deg==16 always)
                c++;
            }
        }
        g_cnt[i] = c;
    }
}

// ---------------------------------------------------------------------------
// Kernel 2: Y[b,i,:] = sum_j w_e * x[b,j,:]   (gather from SMEM-staged x)
// One block per (column-quarter, batch). Dynamic smem:
//   xs[256][64]   : x[b][:, quarter]      (64 KB)
//   sadj[256*16]  : adjacency              (16 KB)
//   sw[256*16]    : edge weights           (16 KB)
//   scnt[256]     : per-dst degree         ( 1 KB)
// 256 threads = 16 col-quads x 16 dst-lanes; each thread does 16 dst.
// ---------------------------------------------------------------------------
#define GATHER_SMEM_FLOATS (NN * 64 + NN * KK * 2 + NN)
#define GATHER_SMEM_BYTES  (GATHER_SMEM_FLOATS * 4)

__global__ __launch_bounds__(256)
void gather_kernel(const float* __restrict__ x)
{
    extern __shared__ float smem[];
    float* xs   = smem;                       // [256][64]
    int*   sadj = (int*)(xs + NN * 64);       // [256*16]
    float* sw   = (float*)(sadj + NN * KK);   // [256*16]
    int*   scnt = (int*)(sw + NN * KK);       // [256]

    const int qtr = blockIdx.x;               // column quarter (0..3)
    const int b   = blockIdx.y;               // batch
    const int t   = threadIdx.x;
    const int c4  = t & 15;                   // col quad within quarter (0..15)
    const int dl  = t >> 4;                   // dst lane (0..15)

    const float* xb = &x[(long)b * NN * TT + qtr * 64];

    // Stage x[b][:, quarter] into smem (coalesced: 16 float4 per node row)
    #pragma unroll
    for (int it = 0; it < 16; it++) {
        int idx  = it * 256 + t;              // 0..4095 float4 slots
        int node = idx >> 4;
        int cc   = idx & 15;
        float4 v = *(const float4*)&xb[node * TT + cc * 4];
        *(float4*)&xs[node * 64 + cc * 4] = v;
    }
    // Stage adjacency
    #pragma unroll
    for (int it = 0; it < 16; it++) {
        int e = it * 256 + t;                 // 0..4095 edges
        sadj[e] = g_adj[e];
        sw[e]   = g_w[e];
    }
    scnt[t] = g_cnt[t];
    __syncthreads();

    float* Yb = &g_Y[(long)b * NN * TT + qtr * 64];

    #pragma unroll
    for (int q = 0; q < 16; q++) {            // 16 dst per thread
        const int ii = dl + q * 16;
        const int c  = scnt[ii];
        float4 acc = make_float4(0.f, 0.f, 0.f, 0.f);
        #pragma unroll
        for (int k = 0; k < KK; k++) {
            if (k < c) {
                int   j = sadj[ii * KK + k];
                float w = sw[ii * KK + k];
                float4 h = *(const float4*)&xs[j * 64 + c4 * 4];
                acc.x = fmaf(w, h.x, acc.x);
                acc.y = fmaf(w, h.y, acc.y);
                acc.z = fmaf(w, h.z, acc.z);
                acc.w = fmaf(w, h.w, acc.w);
            }
        }
        *(float4*)&Yb[ii * TT + c4 * 4] = acc;
    }
}

// ---------------------------------------------------------------------------
// Kernel 3: out = Y @ W + bias   (fp32, packed f32x2 FMA, double-buffered)
// Tile 128x128, K-chunk 16, 256 threads, 8x8 microtile per thread.
// Thread n-mapping is split-fragment (tx*4 and 64+tx*4) so B LDS are
// conflict-free (16 B lane stride -> banks 0..31 contiguous).
// Writes directly to d_out with bias fused in the epilogue (STG.128).
// ---------------------------------------------------------------------------
__device__ __forceinline__ unsigned long long pk2(float lo, float hi) {
    unsigned long long r;
    asm("mov.b64 %0, {%1, %2};" : "=l"(r) : "f"(lo), "f"(hi));
    return r;
}
__device__ __forceinline__ void fma2(unsigned long long& d,
                                     unsigned long long a, unsigned long long b) {
    asm("fma.rn.f32x2 %0, %1, %2, %3;" : "=l"(d) : "l"(a), "l"(b), "l"(d));
}
__device__ __forceinline__ void upk2(unsigned long long v, float& lo, float& hi) {
    asm("mov.b64 {%0, %1}, %2;" : "=f"(lo), "=f"(hi) : "l"(v));
}

#define GA_STRIDE 132   // 128 + 4 pad (mult of 4 -> float4-aligned rows)
#define GB_STRIDE 136   // 128 + 8 pad (mult of 4)

__global__ __launch_bounds__(256, 2)
void gemm_YW_kernel(const float* __restrict__ W,
                    const float* __restrict__ bias,
                    float* __restrict__ out)
{
    __shared__ float Ash[2][16][GA_STRIDE];   // Ash[buf][k][m]
    __shared__ float Bsh[2][16][GB_STRIDE];   // Bsh[buf][k][n]

    const int t   = threadIdx.x;
    const int tx  = t & 15;            // n direction (two 4-wide fragments)
    const int ty  = t >> 4;            // m direction
    const int row0 = blockIdx.y * 128;
    const int n0   = blockIdx.x * 128;

    const float* Y = g_Y;

    // Per-thread global-load assignments (each thread: 2 float4 of A, 2 of B)
    const int am0 = t >> 2,           ak0 = t & 3;
    const int am1 = (t + 256) >> 2,   ak1 = (t + 256) & 3;
    const int bk0 = t >> 5,           bc0 = t & 31;
    const int bk1 = (t + 256) >> 5,   bc1 = (t + 256) & 31;

    // acc[m][0..1] = n-frag0 (cols tx*4..tx*4+3), acc[m][2..3] = n-frag1 (+64)
    unsigned long long acc[8][4];
    #pragma unroll
    for (int m = 0; m < 8; m++)
        #pragma unroll
        for (int p = 0; p < 4; p++) acc[m][p] = 0ULL;

    // ---- prologue: load chunk 0 into buffer 0 ----
    float4 pa0 = *(const float4*)&Y[(row0 + am0) * TT + ak0 * 4];
    float4 pa1 = *(const float4*)&Y[(row0 + am1) * TT + ak1 * 4];
    float4 pb0 = *(const float4*)&W[bk0 * TT + n0 + bc0 * 4];
    float4 pb1 = *(const float4*)&W[bk1 * TT + n0 + bc1 * 4];

    Ash[0][ak0 * 4 + 0][am0] = pa0.x;  Ash[0][ak0 * 4 + 1][am0] = pa0.y;
    Ash[0][ak0 * 4 + 2][am0] = pa0.z;  Ash[0][ak0 * 4 + 3][am0] = pa0.w;
    Ash[0][ak1 * 4 + 0][am1] = pa1.x;  Ash[0][ak1 * 4 + 1][am1] = pa1.y;
    Ash[0][ak1 * 4 + 2][am1] = pa1.z;  Ash[0][ak1 * 4 + 3][am1] = pa1.w;
    *(float4*)&Bsh[0][bk0][bc0 * 4] = pb0;
    *(float4*)&Bsh[0][bk1][bc1 * 4] = pb1;
    __syncthreads();

    int buf = 0;
    for (int k0 = 0; k0 < TT; k0 += 16) {
        const int kn = k0 + 16;
        const bool has_next = (kn < TT);

        // issue next chunk's global loads before compute (latency overlap)
        if (has_next) {
            pa0 = *(const float4*)&Y[(row0 + am0) * TT + kn + ak0 * 4];
            pa1 = *(const float4*)&Y[(row0 + am1) * TT + kn + ak1 * 4];
            pb0 = *(const float4*)&W[(kn + bk0) * TT + n0 + bc0 * 4];
            pb1 = *(const float4*)&W[(kn + bk1) * TT + n0 + bc1 * 4];
        }

        #pragma unroll
        for (int kk = 0; kk < 16; kk++) {
            float4 a0 = *(const float4*)&Ash[buf][kk][ty * 8];
            float4 a1 = *(const float4*)&Ash[buf][kk][ty * 8 + 4];
            // conflict-free B loads: 16 B lane stride, contiguous 256 B region
            float4 bf0 = *(const float4*)&Bsh[buf][kk][tx * 4];
            float4 bf1 = *(const float4*)&Bsh[buf][kk][64 + tx * 4];
            unsigned long long b0 = pk2(bf0.x, bf0.y);
            unsigned long long b1 = pk2(bf0.z, bf0.w);
            unsigned long long b2 = pk2(bf1.x, bf1.y);
            unsigned long long b3 = pk2(bf1.z, bf1.w);
            float am[8] = {a0.x, a0.y, a0.z, a0.w, a1.x, a1.y, a1.z, a1.w};
            #pragma unroll
            for (int m = 0; m < 8; m++) {
                unsigned long long ap = pk2(am[m], am[m]);
                fma2(acc[m][0], ap, b0);
                fma2(acc[m][1], ap, b1);
                fma2(acc[m][2], ap, b2);
                fma2(acc[m][3], ap, b3);
            }
        }

        if (has_next) {
            const int nb = buf ^ 1;
            Ash[nb][ak0 * 4 + 0][am0] = pa0.x;  Ash[nb][ak0 * 4 + 1][am0] = pa0.y;
            Ash[nb][ak0 * 4 + 2][am0] = pa0.z;  Ash[nb][ak0 * 4 + 3][am0] = pa0.w;
            Ash[nb][ak1 * 4 + 0][am1] = pa1.x;  Ash[nb][ak1 * 4 + 1][am1] = pa1.y;
            Ash[nb][ak1 * 4 + 2][am1] = pa1.z;  Ash[nb][ak1 * 4 + 3][am1] = pa1.w;
            *(float4*)&Bsh[nb][bk0][bc0 * 4] = pb0;
            *(float4*)&Bsh[nb][bk1][bc1 * 4] = pb1;
        }
        __syncthreads();
        buf ^= 1;
    }

    // Epilogue: add bias, write directly to out (2x STG.128 per row)
    float bv[8];
    #pragma unroll
    for (int p = 0; p < 4; p++) {
        bv[p]     = bias[n0 + tx * 4 + p];
        bv[4 + p] = bias[n0 + 64 + tx * 4 + p];
    }

    #pragma unroll
    for (int m = 0; m < 8; m++) {
        int row = row0 + ty * 8 + m;
        float v[8];
        #pragma unroll
        for (int p = 0; p < 4; p++) {
            upk2(acc[m][p], v[p * 2], v[p * 2 + 1]);
        }
        #pragma unroll
        for (int p = 0; p < 8; p++) v[p] += bv[p];
        *(float4*)&out[row * TT + n0 + tx * 4]      = make_float4(v[0], v[1], v[2], v[3]);
        *(float4*)&out[row * TT + n0 + 64 + tx * 4] = make_float4(v[4], v[5], v[6], v[7]);
    }
}

// ---------------------------------------------------------------------------
extern "C" void kernel_launch(void* const* d_in, const int* in_sizes, int n_in,
                              void* d_out, int out_size)
{
    const float* x      = (const float*)d_in[0];   // [64,256,256]
    const float* emb    = (const float*)d_in[1];   // [256,64]
    const float* W      = (const float*)d_in[2];   // [256,256]
    const float* bias   = (const float*)d_in[3];   // [256]
    const float* logits = (const float*)d_in[4];   // [65536,2]
    const float* gumbel = (const float*)d_in[5];   // [65536,2]
    float* out = (float*)d_out;

    // Host-side attribute set (non-stream API: capture-safe, deterministic)
    cudaFuncSetAttribute(gather_kernel,
                         cudaFuncAttributeMaxDynamicSharedMemorySize,
                         GATHER_SMEM_BYTES);

    build_graph_kernel<<<NN, 256>>>(emb, logits, gumbel);
    gather_kernel<<<dim3(4, NB), 256, GATHER_SMEM_BYTES>>>(x);
    gemm_YW_kernel<<<dim3(2, 128), 256>>>(W, bias, out);
}

// round 9
// speedup vs baseline: 1.2145x; 1.2145x over previous
#include <cuda_runtime.h>
#include <cuda_bf16.h>
#include <math.h>
#include <float.h>

// Problem constants
#define NB   64          // batch
#define NN   256         // nodes
#define TT   256         // feature dim
#define DD   64          // embedding dim
#define KK   16          // top-k

// Scratch (device globals: no allocation allowed)
__device__ float g_Y[NB * NN * TT];          // 16 MB intermediate Y = A @ x
__device__ float g_EnT[DD * NN];             // normalized emb (transposed)
__device__ int   g_adj[NN * KK];
__device__ float g_w[NN * KK];
__device__ int   g_cnt[NN];

// ---------------------------------------------------------------------------
// Kernel 0: normalized-transposed embedding.
// 1 block x 256 threads. Coalesced LDG staging -> padded smem ->
// per-row norm -> coalesced EnT stores.
// ---------------------------------------------------------------------------
#define PREP_SMEM_BYTES (NN * 65 * 4)

__global__ void prep_emb_kernel(const float* __restrict__ emb)
{
    extern __shared__ float se[];             // [256][65] padded
    const int t = threadIdx.x;

    // Stage 64 KB of emb with fully coalesced float4 loads
    #pragma unroll
    for (int q = 0; q < 16; q++) {
        int li = q * 256 + t;                 // float4 index
        float4 v = *(const float4*)&emb[li * 4];
        int row = li >> 4;
        int col = (li & 15) * 4;
        se[row * 65 + col + 0] = v.x;
        se[row * 65 + col + 1] = v.y;
        se[row * 65 + col + 2] = v.z;
        se[row * 65 + col + 3] = v.w;
    }
    __syncthreads();

    // Row norm (stride-65 smem: bank = (t+d)%32, conflict-free)
    float ss = 0.f;
    #pragma unroll
    for (int d = 0; d < DD; d++) {
        float a = se[t * 65 + d];
        ss = fmaf(a, a, ss);
    }
    const float rn = rsqrtf(ss);

    // EnT[d][t] stores: coalesced across t for each d
    #pragma unroll
    for (int d = 0; d < DD; d++) {
        g_EnT[d * NN + t] = se[t * 65 + d] * rn;
    }
}

// ---------------------------------------------------------------------------
// Kernel 1: build gated kNN graph.
// One block per destination node i; 256 threads compute cos (coalesced via
// EnT; row-i norm fused into the dot loop); warp 0 alone does the 16-round
// argmax in registers (no block barriers in the selection loop).
// ---------------------------------------------------------------------------
__global__ void build_graph_kernel(const float* __restrict__ emb,
                                   const float* __restrict__ logits,
                                   const float* __restrict__ gumbel)
{
    const int i    = blockIdx.x;
    const int t    = threadIdx.x;
    const int lane = t & 31;
    const int warp = t >> 5;

    __shared__ float si[DD];      // raw emb row i
    __shared__ float wv[NN];      // cos values
    __shared__ int   sel[KK];
    __shared__ float sgate[KK];

    if (t < DD) si[t] = emb[i * DD + t];      // coalesced: 2 lines
    __syncthreads();

    // cos(i, t): si[d] smem broadcast, EnT[d*256+t] coalesced LDG.
    // Row-i norm computed redundantly per thread (broadcast FMAs: free slots).
    float dot = 0.f, ss = 0.f;
    #pragma unroll
    for (int d = 0; d < DD; d++) {
        float a = si[d];
        dot = fmaf(a, g_EnT[d * NN + t], dot);
        ss  = fmaf(a, a, ss);
    }
    wv[t] = dot * rsqrtf(ss);
    __syncthreads();

    if (warp == 0) {
        // 8 candidate values per lane, register-resident
        float v[8];
        #pragma unroll
        for (int m = 0; m < 8; m++) v[m] = wv[m * 32 + lane];

        // 16 rounds of warp argmax (tie -> lower index, matching jax top_k)
        for (int r = 0; r < KK; r++) {
            float bv = v[0];
            int   bm = 0;
            #pragma unroll
            for (int m = 1; m < 8; m++) {
                if (v[m] > bv) { bv = v[m]; bm = m; }   // strict >: keeps lowest m
            }
            int bidx = bm * 32 + lane;
            #pragma unroll
            for (int s = 16; s > 0; s >>= 1) {
                float ov = __shfl_down_sync(0xffffffffu, bv, s);
                int   oi = __shfl_down_sync(0xffffffffu, bidx, s);
                if (ov > bv || (ov == bv && oi < bidx)) { bv = ov; bidx = oi; }
            }
            bidx = __shfl_sync(0xffffffffu, bidx, 0);   // broadcast winner
            if (lane == 0) sel[r] = bidx;
            if ((bidx & 31) == lane) v[bidx >> 5] = -FLT_MAX;  // owner invalidates
        }
        __syncwarp();

        // Gumbel-softmax hard gate per selected edge (lanes 0..15)
        if (lane < KK) {
            int j = sel[lane];
            long idx = (long)i * NN + j;
            float u0 = gumbel[idx * 2 + 0];
            float u1 = gumbel[idx * 2 + 1];
            float g0 = -logf(-logf(u0));
            float g1 = -logf(-logf(u1));
            float v0 = logits[idx * 2 + 0] + g0;
            float v1 = logits[idx * 2 + 1] + g1;
            float m  = fmaxf(v0, v1);
            float e0 = expf(v0 - m), e1 = expf(v1 - m);
            float s0 = e0 / (e0 + e1);
            float hard0 = (v0 >= v1) ? 1.0f : 0.0f;   // argmax ties -> index 0
            float gate = (hard0 + s0) - s0;           // straight-through forward value
            sgate[lane] = gate;
        }
        __syncwarp();

        // Deterministic compaction (stable fp sum order downstream)
        if (lane == 0) {
            int c = 0;
            for (int r = 0; r < KK; r++) {
                if (sgate[r] > 0.5f) {
                    g_adj[i * KK + c] = sel[r];
                    g_w[i * KK + c]   = 0.0625f * sgate[r];  // dinv_src*dinv_dst = 1/16 (deg==16)
                    c++;
                }
            }
            g_cnt[i] = c;
        }
    }
}

// ---------------------------------------------------------------------------
// Kernel 2: Y[b,i,:] = sum_j w_e * x[b,j,:]   (gather from SMEM-staged x)
// One block per (column-quarter, batch).
// ---------------------------------------------------------------------------
#define GATHER_SMEM_FLOATS (NN * 64 + NN * KK * 2 + NN)
#define GATHER_SMEM_BYTES  (GATHER_SMEM_FLOATS * 4)

__global__ __launch_bounds__(256)
void gather_kernel(const float* __restrict__ x)
{
    extern __shared__ float smem[];
    float* xs   = smem;                       // [256][64]
    int*   sadj = (int*)(xs + NN * 64);       // [256*16]
    float* sw   = (float*)(sadj + NN * KK);   // [256*16]
    int*   scnt = (int*)(sw + NN * KK);       // [256]

    const int qtr = blockIdx.x;               // column quarter (0..3)
    const int b   = blockIdx.y;               // batch
    const int t   = threadIdx.x;
    const int c4  = t & 15;                   // col quad within quarter (0..15)
    const int dl  = t >> 4;                   // dst lane (0..15)

    const float* xb = &x[(long)b * NN * TT + qtr * 64];

    // Stage x[b][:, quarter] into smem (coalesced: 16 float4 per node row)
    #pragma unroll
    for (int it = 0; it < 16; it++) {
        int idx  = it * 256 + t;              // 0..4095 float4 slots
        int node = idx >> 4;
        int cc   = idx & 15;
        float4 v = *(const float4*)&xb[node * TT + cc * 4];
        *(float4*)&xs[node * 64 + cc * 4] = v;
    }
    // Stage adjacency
    #pragma unroll
    for (int it = 0; it < 16; it++) {
        int e = it * 256 + t;                 // 0..4095 edges
        sadj[e] = g_adj[e];
        sw[e]   = g_w[e];
    }
    scnt[t] = g_cnt[t];
    __syncthreads();

    float* Yb = &g_Y[(long)b * NN * TT + qtr * 64];

    #pragma unroll
    for (int q = 0; q < 16; q++) {            // 16 dst per thread
        const int ii = dl + q * 16;
        const int c  = scnt[ii];
        float4 acc = make_float4(0.f, 0.f, 0.f, 0.f);
        #pragma unroll
        for (int k = 0; k < KK; k++) {
            if (k < c) {
                int   j = sadj[ii * KK + k];
                float w = sw[ii * KK + k];
                float4 h = *(const float4*)&xs[j * 64 + c4 * 4];
                acc.x = fmaf(w, h.x, acc.x);
                acc.y = fmaf(w, h.y, acc.y);
                acc.z = fmaf(w, h.z, acc.z);
                acc.w = fmaf(w, h.w, acc.w);
            }
        }
        *(float4*)&Yb[ii * TT + c4 * 4] = acc;
    }
}

// ---------------------------------------------------------------------------
// Kernel 3: out = Y @ W + bias   (fp32, packed f32x2 FMA, double-buffered)
// Tile 128x128, K-chunk 16, 256 threads, 8x8 microtile per thread.
// Split-fragment n-mapping (tx*4 and 64+tx*4): conflict-free B LDS.
// ---------------------------------------------------------------------------
__device__ __forceinline__ unsigned long long pk2(float lo, float hi) {
    unsigned long long r;
    asm("mov.b64 %0, {%1, %2};" : "=l"(r) : "f"(lo), "f"(hi));
    return r;
}
__device__ __forceinline__ void fma2(unsigned long long& d,
                                     unsigned long long a, unsigned long long b) {
    asm("fma.rn.f32x2 %0, %1, %2, %3;" : "=l"(d) : "l"(a), "l"(b), "l"(d));
}
__device__ __forceinline__ void upk2(unsigned long long v, float& lo, float& hi) {
    asm("mov.b64 {%0, %1}, %2;" : "=f"(lo), "=f"(hi) : "l"(v));
}

#define GA_STRIDE 132   // 128 + 4 pad
#define GB_STRIDE 136   // 128 + 8 pad

__global__ __launch_bounds__(256, 2)
void gemm_YW_kernel(const float* __restrict__ W,
                    const float* __restrict__ bias,
                    float* __restrict__ out)
{
    __shared__ float Ash[2][16][GA_STRIDE];   // Ash[buf][k][m]
    __shared__ float Bsh[2][16][GB_STRIDE];   // Bsh[buf][k][n]

    const int t   = threadIdx.x;
    const int tx  = t & 15;            // n direction (two 4-wide fragments)
    const int ty  = t >> 4;            // m direction
    const int row0 = blockIdx.y * 128;
    const int n0   = blockIdx.x * 128;

    const float* Y = g_Y;

    const int am0 = t >> 2,           ak0 = t & 3;
    const int am1 = (t + 256) >> 2,   ak1 = (t + 256) & 3;
    const int bk0 = t >> 5,           bc0 = t & 31;
    const int bk1 = (t + 256) >> 5,   bc1 = (t + 256) & 31;

    unsigned long long acc[8][4];
    #pragma unroll
    for (int m = 0; m < 8; m++)
        #pragma unroll
        for (int p = 0; p < 4; p++) acc[m][p] = 0ULL;

    // ---- prologue: load chunk 0 into buffer 0 ----
    float4 pa0 = *(const float4*)&Y[(row0 + am0) * TT + ak0 * 4];
    float4 pa1 = *(const float4*)&Y[(row0 + am1) * TT + ak1 * 4];
    float4 pb0 = *(const float4*)&W[bk0 * TT + n0 + bc0 * 4];
    float4 pb1 = *(const float4*)&W[bk1 * TT + n0 + bc1 * 4];

    Ash[0][ak0 * 4 + 0][am0] = pa0.x;  Ash[0][ak0 * 4 + 1][am0] = pa0.y;
    Ash[0][ak0 * 4 + 2][am0] = pa0.z;  Ash[0][ak0 * 4 + 3][am0] = pa0.w;
    Ash[0][ak1 * 4 + 0][am1] = pa1.x;  Ash[0][ak1 * 4 + 1][am1] = pa1.y;
    Ash[0][ak1 * 4 + 2][am1] = pa1.z;  Ash[0][ak1 * 4 + 3][am1] = pa1.w;
    *(float4*)&Bsh[0][bk0][bc0 * 4] = pb0;
    *(float4*)&Bsh[0][bk1][bc1 * 4] = pb1;
    __syncthreads();

    int buf = 0;
    for (int k0 = 0; k0 < TT; k0 += 16) {
        const int kn = k0 + 16;
        const bool has_next = (kn < TT);

        if (has_next) {
            pa0 = *(const float4*)&Y[(row0 + am0) * TT + kn + ak0 * 4];
            pa1 = *(const float4*)&Y[(row0 + am1) * TT + kn + ak1 * 4];
            pb0 = *(const float4*)&W[(kn + bk0) * TT + n0 + bc0 * 4];
            pb1 = *(const float4*)&W[(kn + bk1) * TT + n0 + bc1 * 4];
        }

        #pragma unroll
        for (int kk = 0; kk < 16; kk++) {
            float4 a0 = *(const float4*)&Ash[buf][kk][ty * 8];
            float4 a1 = *(const float4*)&Ash[buf][kk][ty * 8 + 4];
            // conflict-free B loads, native u64 pairs
            ulonglong2 bq0 = *(const ulonglong2*)&Bsh[buf][kk][tx * 4];
            ulonglong2 bq1 = *(const ulonglong2*)&Bsh[buf][kk][64 + tx * 4];
            unsigned long long b0 = bq0.x, b1 = bq0.y,
                               b2 = bq1.x, b3 = bq1.y;
            float am[8] = {a0.x, a0.y, a0.z, a0.w, a1.x, a1.y, a1.z, a1.w};
            #pragma unroll
            for (int m = 0; m < 8; m++) {
                unsigned long long ap = pk2(am[m], am[m]);
                fma2(acc[m][0], ap, b0);
                fma2(acc[m][1], ap, b1);
                fma2(acc[m][2], ap, b2);
                fma2(acc[m][3], ap, b3);
            }
        }

        if (has_next) {
            const int nb = buf ^ 1;
            Ash[nb][ak0 * 4 + 0][am0] = pa0.x;  Ash[nb][ak0 * 4 + 1][am0] = pa0.y;
            Ash[nb][ak0 * 4 + 2][am0] = pa0.z;  Ash[nb][ak0 * 4 + 3][am0] = pa0.w;
            Ash[nb][ak1 * 4 + 0][am1] = pa1.x;  Ash[nb][ak1 * 4 + 1][am1] = pa1.y;
            Ash[nb][ak1 * 4 + 2][am1] = pa1.z;  Ash[nb][ak1 * 4 + 3][am1] = pa1.w;
            *(float4*)&Bsh[nb][bk0][bc0 * 4] = pb0;
            *(float4*)&Bsh[nb][bk1][bc1 * 4] = pb1;
        }
        __syncthreads();
        buf ^= 1;
    }

    // Epilogue: add bias, write directly to out (2x STG.128 per row)
    float bv[8];
    #pragma unroll
    for (int p = 0; p < 4; p++) {
        bv[p]     = bias[n0 + tx * 4 + p];
        bv[4 + p] = bias[n0 + 64 + tx * 4 + p];
    }

    #pragma unroll
    for (int m = 0; m < 8; m++) {
        int row = row0 + ty * 8 + m;
        float v[8];
        #pragma unroll
        for (int p = 0; p < 4; p++) {
            upk2(acc[m][p], v[p * 2], v[p * 2 + 1]);
        }
        #pragma unroll
        for (int p = 0; p < 8; p++) v[p] += bv[p];
        *(float4*)&out[row * TT + n0 + tx * 4]      = make_float4(v[0], v[1], v[2], v[3]);
        *(float4*)&out[row * TT + n0 + 64 + tx * 4] = make_float4(v[4], v[5], v[6], v[7]);
    }
}

// ---------------------------------------------------------------------------
extern "C" void kernel_launch(void* const* d_in, const int* in_sizes, int n_in,
                              void* d_out, int out_size)
{
    const float* x      = (const float*)d_in[0];   // [64,256,256]
    const float* emb    = (const float*)d_in[1];   // [256,64]
    const float* W      = (const float*)d_in[2];   // [256,256]
    const float* bias   = (const float*)d_in[3];   // [256]
    const float* logits = (const float*)d_in[4];   // [65536,2]
    const float* gumbel = (const float*)d_in[5];   // [65536,2]
    float* out = (float*)d_out;

    // Host-side attribute sets (non-stream API: capture-safe, deterministic)
    cudaFuncSetAttribute(prep_emb_kernel,
                         cudaFuncAttributeMaxDynamicSharedMemorySize,
                         PREP_SMEM_BYTES);
    cudaFuncSetAttribute(gather_kernel,
                         cudaFuncAttributeMaxDynamicSharedMemorySize,
                         GATHER_SMEM_BYTES);

    prep_emb_kernel<<<1, 256, PREP_SMEM_BYTES>>>(emb);
    build_graph_kernel<<<NN, 256>>>(emb, logits, gumbel);
    gather_kernel<<<dim3(4, NB), 256, GATHER_SMEM_BYTES>>>(x);
    gemm_YW_kernel<<<dim3(2, 128), 256>>>(W, bias, out);
}